// round 14
// baseline (speedup 1.0000x reference)
#include <cuda_runtime.h>
#include <math.h>

#define L_TOTAL 131072
#define NBATCH  8
#define CHUNK   16
#define FWARM   48
#define ENVW    192
#define SKEW    8
#define NCHUNK  (L_TOTAL / CHUNK)            // 8192
#define NTHREADS (NCHUNK * NBATCH)           // 65536
#define BLOCK   512                          // 4 warps per SMSP (RF-capped max)
#define ITERS   (CHUNK + FWARM + SKEW)       // 72
#define WSTART  (FWARM + SKEW)               // 56

__device__ __forceinline__ float ex2a(float x) {
    float y; asm("ex2.approx.ftz.f32 %0, %1;" : "=f"(y) : "f"(x)); return y;
}
__device__ __forceinline__ float rcpa(float x) {
    float y; asm("rcp.approx.ftz.f32 %0, %1;" : "=f"(y) : "f"(x)); return y;
}

struct Coef { float b0, b1, b2, a1, a2; };

__device__ __forceinline__ float bqstep(const Coef& c, float x, float& s1, float& s2) {
    float y = fmaf(c.b0, x, s1);
    float t = fmaf(c.b1, x, s2);
    s1 = fmaf(-c.a1, y, t);
    s2 = fmaf(-c.a2, y, c.b2 * x);
    return y;
}

__device__ __forceinline__ Coef mk_stable(float r0, float r1, float r2, float r3, float r4) {
    float a1 = 2.f * tanhf(r3);
    float aa = fabsf(a1);
    float a2 = 0.5f * fmaf(2.f - aa, tanhf(r4), aa);
    Coef c; c.b0 = r0; c.b1 = r1; c.b2 = r2; c.a1 = a1; c.a2 = a2;
    return c;
}

struct GruC {
    float rwx, rwh, rc, zwx, zwh, zc, wi2n, bi2n, wh2n, bh2n, ow, ob;
};

// One pipeline step. GUARDED enables the GRU-start predicated select.
template<bool GUARDED>
__device__ __forceinline__ float pipe_step(
    float xv, int it, int gg,
    const Coef& c1, const Coef& c2, const Coef& c3, const Coef& c4, const Coef& cf,
    const GruC& G, float cenv, float ccenv, float depth, float fbmix,
    float& env, float& h,
    float& d0, float& d1, float& d2, float& d3,
    float& d4, float& d5, float& d6, float& d7,
    float& s11, float& s12, float& s21, float& s22,
    float& s31, float& s32, float& s41, float& s42,
    float& sf1, float& sf2)
{
    float y1 = bqstep(c1, d0, s11, s12);
    float y2 = bqstep(c2, d1, s21, s22);

    // GRU (chain ~92 cyc): FFMA->EX2->FADD->RCP->FFMA->EX2->FADD->RCP->FFMA->FADD->FFMA
    float er = ex2a(fmaf(h, G.rwh, fmaf(d2, G.rwx, G.rc)));
    float ez = ex2a(fmaf(h, G.zwh, fmaf(d2, G.zwx, G.zc)));
    float r = rcpa(1.f + er);
    float z = rcpa(1.f + ez);
    float gi2s = fmaf(d2, G.wi2n, G.bi2n);
    float gh2s = fmaf(h, G.wh2n, G.bh2n);
    float en = ex2a(fmaf(r, gh2s, gi2s));
    float n = fmaf(2.f, rcpa(1.f + en), -1.f);
    float hn = fmaf(z, h - n, n);
    if (GUARDED) h = (it >= gg) ? hn : 0.f;   // predicated select, no branch
    else         h = hn;
    float y3 = fmaf(h, G.ow, G.ob);

    float y4 = bqstep(c3, d3, s31, s32);
    float y5 = bqstep(c4, d4, s41, s42);
    float yfb = bqstep(cf, d7, sf1, sf2);
    float ov = fmaf(-fbmix, yfb, d7);

    env = fmaf(cenv, env, ccenv * fabsf(xv));
    float y0 = xv * fmaf(-depth, env, 1.f);

    d7 = d6; d6 = d5; d5 = y5; d4 = y4; d3 = y3; d2 = y2; d1 = y1; d0 = y0;
    return ov;
}

__global__ void __launch_bounds__(BLOCK, 1) amp_kernel(
    const float* __restrict__ X,     const float* __restrict__ knobs,
    const float* __restrict__ ecr,   const float* __restrict__ prep,
    const float* __restrict__ postp, const float* __restrict__ gwi,
    const float* __restrict__ gwh,   const float* __restrict__ gbi,
    const float* __restrict__ gbh,   const float* __restrict__ gow,
    const float* __restrict__ gob,   const float* __restrict__ sw1,
    const float* __restrict__ sb1,   const float* __restrict__ sw2,
    const float* __restrict__ sb2,   const float* __restrict__ fw1,
    const float* __restrict__ fb1,   const float* __restrict__ fw2,
    const float* __restrict__ fb2,   const float* __restrict__ famt,
    float* __restrict__ OUT)
{
    const int tid = blockIdx.x * BLOCK + threadIdx.x;
    if (tid >= NTHREADS) return;
    // whole warp on ONE batch row, adjacent lanes on adjacent chunks
    const int b  = tid >> 13;                 // tid / NCHUNK
    const int cp = tid & (NCHUNK - 1);

    // ---------------- per-batch setup ----------------
    const float cenv  = 1.f / (1.f + expf(-ecr[0]));
    const float ccenv = 1.f - cenv;

    const float k0 = knobs[b * 3 + 0];
    float acc = sb2[0];
#pragma unroll
    for (int j = 0; j < 8; j++) acc += sw2[j] * tanhf(fmaf(k0, sw1[j], sb1[j]));
    const float depth = 1.f / (1.f + expf(-acc));

    const Coef c1 = mk_stable(prep[0], prep[1], prep[2], prep[3], prep[4]);
    const Coef c2 = mk_stable(prep[5], prep[6], prep[7], prep[8], prep[9]);
    const Coef c3 = mk_stable(postp[0], postp[1], postp[2], postp[3], postp[4]);
    const Coef c4 = mk_stable(postp[5], postp[6], postp[7], postp[8], postp[9]);

    Coef cf;
    {
        const float k1 = knobs[b * 3 + 1], k2 = knobs[b * 3 + 2];
        float h16[16];
#pragma unroll
        for (int j = 0; j < 16; j++)
            h16[j] = tanhf(fmaf(k1, fw1[j * 2 + 0], fmaf(k2, fw1[j * 2 + 1], fb1[j])));
        float raw[5];
#pragma unroll
        for (int i = 0; i < 5; i++) {
            float a = fb2[i];
#pragma unroll
            for (int j = 0; j < 16; j++) a = fmaf(fw2[i * 16 + j], h16[j], a);
            raw[i] = a;
        }
        cf = mk_stable(raw[0], raw[1], raw[2], raw[3], raw[4]);
    }
    const float fbmix = 1.f / (1.f + expf(-famt[0]));

    const float L2E = 1.4426950408889634f;
    const float NL2E = -2.f * L2E;
    GruC G;
    G.rwx = -L2E * gwi[0]; G.rwh = -L2E * gwh[0]; G.rc = -L2E * (gbi[0] + gbh[0]);
    G.zwx = -L2E * gwi[1]; G.zwh = -L2E * gwh[1]; G.zc = -L2E * (gbi[1] + gbh[1]);
    G.wi2n = NL2E * gwi[2]; G.bi2n = NL2E * gbi[2];
    G.wh2n = NL2E * gwh[2]; G.bh2n = NL2E * gbh[2];
    G.ow = gow[0]; G.ob = gob[0];

    const float* __restrict__ xr = X + (size_t)b * L_TOTAL;
    float* __restrict__ orow     = OUT + (size_t)b * L_TOTAL;

    // ---------------- stream state ----------------
    const int fb = cp * CHUNK - FWARM;            // 16-aligned, may be negative
    int gg = 3 - fb; if (gg < 3) gg = 3;          // GRU start iter (max 51 < WSTART=56)

    float env = 0.f, h = 0.f;
    float d0 = 0.f, d1 = 0.f, d2 = 0.f, d3 = 0.f;
    float d4 = 0.f, d5 = 0.f, d6 = 0.f, d7 = 0.f;
    float s11 = 0.f, s12 = 0.f, s21 = 0.f, s22 = 0.f;
    float s31 = 0.f, s32 = 0.f, s41 = 0.f, s42 = 0.f, sf1 = 0.f, sf2 = 0.f;

    // ---------------- exact envelope pre-scan (zero-history exact) ----------------
    {
        const float cc2 = cenv * cenv, cc4 = cc2 * cc2;
        const float g0 = ccenv * cenv * cc2;
        const float g1 = ccenv * cc2;
        const float g2 = ccenv * cenv;
        const float g3 = ccenv;
        int t0 = fb - ENVW; if (t0 < 0) t0 = 0;
        float e = 0.f;
        for (int t = t0; t < fb; t += 4) {
            float4 v = *reinterpret_cast<const float4*>(xr + t);
            float a = g0 * fabsf(v.x);
            a = fmaf(g1, fabsf(v.y), a);
            a = fmaf(g2, fabsf(v.z), a);
            a = fmaf(g3, fabsf(v.w), a);
            e = fmaf(cc4, e, a);
        }
        env = e;
    }

#define PSTEP(G_, xv_, it_) pipe_step<G_>(xv_, it_, gg, c1, c2, c3, c4, cf, G, \
        cenv, ccenv, depth, fbmix, env, h, d0, d1, d2, d3, d4, d5, d6, d7,     \
        s11, s12, s21, s22, s31, s32, s41, s42, sf1, sf2)

    // ---------------- prologue (SKEW scalar iters, select-guarded) ----------------
#pragma unroll
    for (int i = 0; i < SKEW; i++) {
        int s = fb + i;
        int sa = s < 0 ? 0 : s;
        float xv = xr[sa];
        xv = (s >= 0) ? xv : 0.f;
        (void)PSTEP(true, xv, i);
    }

    // ---------------- warm loop (no stores, masked loads, guarded GRU) ----------------
    for (int i = SKEW; i < WSTART; i += 4) {
        int s = fb + i;
        int sa = s < 0 ? 0 : s;                   // 4-aligned groups: all-in or all-out
        float4 v = *reinterpret_cast<const float4*>(xr + sa);
        float m = (s >= 0) ? 1.f : 0.f;
        float xv4[4] = { v.x * m, v.y * m, v.z * m, v.w * m };
#pragma unroll
        for (int j = 0; j < 4; j++)
            (void)PSTEP(true, xv4[j], i + j);
    }

    // ---------------- output loop (unconditional stores, clean body) ----------------
    for (int i = WSTART; i < ITERS; i += 4) {
        int s = fb + i;
        int sa = s > (L_TOTAL - 4) ? (L_TOTAL - 4) : s;  // tail over-read is dead data
        float4 v = *reinterpret_cast<const float4*>(xr + sa);
        float xv4[4] = { v.x, v.y, v.z, v.w };
        float ov4[4];
#pragma unroll
        for (int j = 0; j < 4; j++)
            ov4[j] = PSTEP(false, xv4[j], i + j);
        float4 o; o.x = ov4[0]; o.y = ov4[1]; o.z = ov4[2]; o.w = ov4[3];
        *reinterpret_cast<float4*>(orow + (s - SKEW)) = o;
    }
#undef PSTEP
}

extern "C" void kernel_launch(void* const* d_in, const int* in_sizes, int n_in,
                              void* d_out, int out_size)
{
    const float* X     = (const float*)d_in[0];
    const float* knobs = (const float*)d_in[1];
    const float* ecr   = (const float*)d_in[2];
    const float* prep  = (const float*)d_in[3];
    const float* postp = (const float*)d_in[4];
    const float* gwi   = (const float*)d_in[5];
    const float* gwh   = (const float*)d_in[6];
    const float* gbi   = (const float*)d_in[7];
    const float* gbh   = (const float*)d_in[8];
    const float* gow   = (const float*)d_in[9];
    const float* gob   = (const float*)d_in[10];
    const float* sw1   = (const float*)d_in[11];
    const float* sb1   = (const float*)d_in[12];
    const float* sw2   = (const float*)d_in[13];
    const float* sb2   = (const float*)d_in[14];
    const float* fw1   = (const float*)d_in[15];
    const float* fb1   = (const float*)d_in[16];
    const float* fw2   = (const float*)d_in[17];
    const float* fb2   = (const float*)d_in[18];
    const float* famt  = (const float*)d_in[19];
    float* OUT = (float*)d_out;

    dim3 grid(NTHREADS / BLOCK);   // 128 blocks x 512 threads: 4 warps per SMSP
    amp_kernel<<<grid, BLOCK>>>(X, knobs, ecr, prep, postp, gwi, gwh, gbi, gbh,
                                gow, gob, sw1, sb1, sw2, sb2, fw1, fb1, fw2, fb2,
                                famt, OUT);
}

// round 16
// speedup vs baseline: 1.4421x; 1.4421x over previous
#include <cuda_runtime.h>
#include <math.h>

#define L_TOTAL 131072
#define NBATCH  8
#define CHUNK   16
#define FWARM   48
#define ENVW    192
#define SKEW    8
#define NCHUNK  (L_TOTAL / CHUNK)            // 8192
#define NTHREADS (NCHUNK * NBATCH)           // 65536
#define BLOCK   512                          // 4 warps per SMSP (RF-capped max)
#define ITERS   (CHUNK + FWARM + SKEW)       // 72
#define WSTART  (FWARM + SKEW)               // 56

__device__ __forceinline__ float ex2a(float x) {
    float y; asm("ex2.approx.ftz.f32 %0, %1;" : "=f"(y) : "f"(x)); return y;
}
__device__ __forceinline__ float rcpa(float x) {
    float y; asm("rcp.approx.ftz.f32 %0, %1;" : "=f"(y) : "f"(x)); return y;
}

struct Coef { float b0, b1, b2, a1, a2; };

__device__ __forceinline__ float bqstep(const Coef& c, float x, float& s1, float& s2) {
    float y = fmaf(c.b0, x, s1);
    float t = fmaf(c.b1, x, s2);
    s1 = fmaf(-c.a1, y, t);
    s2 = fmaf(-c.a2, y, c.b2 * x);
    return y;
}

__device__ __forceinline__ Coef mk_stable(float r0, float r1, float r2, float r3, float r4) {
    float a1 = 2.f * tanhf(r3);
    float aa = fabsf(a1);
    float a2 = 0.5f * fmaf(2.f - aa, tanhf(r4), aa);
    Coef c; c.b0 = r0; c.b1 = r1; c.b2 = r2; c.a1 = a1; c.a2 = a2;
    return c;
}

struct GruC {
    float rwx, rwh, rc, zwx, zwh, zc, wi2n, bi2n, wh2n, bh2n, ow, ob;
};

// One pipeline step. GUARDED enables the GRU-start predicated select.
template<bool GUARDED>
__device__ __forceinline__ float pipe_step(
    float xv, int it, int gg,
    const Coef& c1, const Coef& c2, const Coef& c3, const Coef& c4, const Coef& cf,
    const GruC& G, float cenv, float ccenv, float depth, float fbmix,
    float& env, float& h,
    float& d0, float& d1, float& d2, float& d3,
    float& d4, float& d5, float& d6, float& d7,
    float& s11, float& s12, float& s21, float& s22,
    float& s31, float& s32, float& s41, float& s42,
    float& sf1, float& sf2)
{
    float y1 = bqstep(c1, d0, s11, s12);
    float y2 = bqstep(c2, d1, s21, s22);

    // GRU (chain ~92 cyc): FFMA->EX2->FADD->RCP->FFMA->EX2->FADD->RCP->FFMA->FADD->FFMA
    float er = ex2a(fmaf(h, G.rwh, fmaf(d2, G.rwx, G.rc)));
    float ez = ex2a(fmaf(h, G.zwh, fmaf(d2, G.zwx, G.zc)));
    float r = rcpa(1.f + er);
    float z = rcpa(1.f + ez);
    float gi2s = fmaf(d2, G.wi2n, G.bi2n);
    float gh2s = fmaf(h, G.wh2n, G.bh2n);
    float en = ex2a(fmaf(r, gh2s, gi2s));
    float n = fmaf(2.f, rcpa(1.f + en), -1.f);
    float hn = fmaf(z, h - n, n);
    if (GUARDED) h = (it >= gg) ? hn : 0.f;   // predicated select, no branch
    else         h = hn;
    float y3 = fmaf(h, G.ow, G.ob);

    float y4 = bqstep(c3, d3, s31, s32);
    float y5 = bqstep(c4, d4, s41, s42);
    float yfb = bqstep(cf, d7, sf1, sf2);
    float ov = fmaf(-fbmix, yfb, d7);

    env = fmaf(cenv, env, ccenv * fabsf(xv));
    float y0 = xv * fmaf(-depth, env, 1.f);

    d7 = d6; d6 = d5; d5 = y5; d4 = y4; d3 = y3; d2 = y2; d1 = y1; d0 = y0;
    return ov;
}

__global__ void __launch_bounds__(BLOCK, 1) amp_kernel(
    const float* __restrict__ X,     const float* __restrict__ knobs,
    const float* __restrict__ ecr,   const float* __restrict__ prep,
    const float* __restrict__ postp, const float* __restrict__ gwi,
    const float* __restrict__ gwh,   const float* __restrict__ gbi,
    const float* __restrict__ gbh,   const float* __restrict__ gow,
    const float* __restrict__ gob,   const float* __restrict__ sw1,
    const float* __restrict__ sb1,   const float* __restrict__ sw2,
    const float* __restrict__ sb2,   const float* __restrict__ fw1,
    const float* __restrict__ fb1,   const float* __restrict__ fw2,
    const float* __restrict__ fb2,   const float* __restrict__ famt,
    float* __restrict__ OUT)
{
    const int tid = blockIdx.x * BLOCK + threadIdx.x;
    if (tid >= NTHREADS) return;
    // whole warp on ONE batch row, adjacent lanes on adjacent chunks
    const int b  = tid >> 13;                 // tid / NCHUNK
    const int cp = tid & (NCHUNK - 1);

    // ---------------- per-batch setup ----------------
    const float cenv  = 1.f / (1.f + expf(-ecr[0]));
    const float ccenv = 1.f - cenv;

    const float k0 = knobs[b * 3 + 0];
    float acc = sb2[0];
#pragma unroll
    for (int j = 0; j < 8; j++) acc += sw2[j] * tanhf(fmaf(k0, sw1[j], sb1[j]));
    const float depth = 1.f / (1.f + expf(-acc));

    const Coef c1 = mk_stable(prep[0], prep[1], prep[2], prep[3], prep[4]);
    const Coef c2 = mk_stable(prep[5], prep[6], prep[7], prep[8], prep[9]);
    const Coef c3 = mk_stable(postp[0], postp[1], postp[2], postp[3], postp[4]);
    const Coef c4 = mk_stable(postp[5], postp[6], postp[7], postp[8], postp[9]);

    Coef cf;
    {
        const float k1 = knobs[b * 3 + 1], k2 = knobs[b * 3 + 2];
        float h16[16];
#pragma unroll
        for (int j = 0; j < 16; j++)
            h16[j] = tanhf(fmaf(k1, fw1[j * 2 + 0], fmaf(k2, fw1[j * 2 + 1], fb1[j])));
        float raw[5];
#pragma unroll
        for (int i = 0; i < 5; i++) {
            float a = fb2[i];
#pragma unroll
            for (int j = 0; j < 16; j++) a = fmaf(fw2[i * 16 + j], h16[j], a);
            raw[i] = a;
        }
        cf = mk_stable(raw[0], raw[1], raw[2], raw[3], raw[4]);
    }
    const float fbmix = 1.f / (1.f + expf(-famt[0]));

    const float L2E = 1.4426950408889634f;
    const float NL2E = -2.f * L2E;
    GruC G;
    G.rwx = -L2E * gwi[0]; G.rwh = -L2E * gwh[0]; G.rc = -L2E * (gbi[0] + gbh[0]);
    G.zwx = -L2E * gwi[1]; G.zwh = -L2E * gwh[1]; G.zc = -L2E * (gbi[1] + gbh[1]);
    G.wi2n = NL2E * gwi[2]; G.bi2n = NL2E * gbi[2];
    G.wh2n = NL2E * gwh[2]; G.bh2n = NL2E * gbh[2];
    G.ow = gow[0]; G.ob = gob[0];

    const float* __restrict__ xr = X + (size_t)b * L_TOTAL;
    float* __restrict__ orow     = OUT + (size_t)b * L_TOTAL;

    // ---------------- stream state ----------------
    const int fb = cp * CHUNK - FWARM;            // 16-aligned, may be negative
    int gg = 3 - fb; if (gg < 3) gg = 3;          // GRU start iter (max 51 < WSTART=56)

    float env = 0.f, h = 0.f;
    float d0 = 0.f, d1 = 0.f, d2 = 0.f, d3 = 0.f;
    float d4 = 0.f, d5 = 0.f, d6 = 0.f, d7 = 0.f;
    float s11 = 0.f, s12 = 0.f, s21 = 0.f, s22 = 0.f;
    float s31 = 0.f, s32 = 0.f, s41 = 0.f, s42 = 0.f, sf1 = 0.f, sf2 = 0.f;

    // ---------------- exact envelope pre-scan (zero-history exact) ----------------
    {
        const float cc2 = cenv * cenv, cc4 = cc2 * cc2;
        const float g0 = ccenv * cenv * cc2;
        const float g1 = ccenv * cc2;
        const float g2 = ccenv * cenv;
        const float g3 = ccenv;
        int t0 = fb - ENVW; if (t0 < 0) t0 = 0;
        float e = 0.f;
#pragma unroll 1
        for (int t = t0; t < fb; t += 4) {
            float4 v = *reinterpret_cast<const float4*>(xr + t);
            float a = g0 * fabsf(v.x);
            a = fmaf(g1, fabsf(v.y), a);
            a = fmaf(g2, fabsf(v.z), a);
            a = fmaf(g3, fabsf(v.w), a);
            e = fmaf(cc4, e, a);
        }
        env = e;
    }

#define PSTEP(G_, xv_, it_) pipe_step<G_>(xv_, it_, gg, c1, c2, c3, c4, cf, G, \
        cenv, ccenv, depth, fbmix, env, h, d0, d1, d2, d3, d4, d5, d6, d7,     \
        s11, s12, s21, s22, s31, s32, s41, s42, sf1, sf2)

    // ---------------- prologue (SKEW scalar iters, select-guarded, ROLLED) ----------------
#pragma unroll 1
    for (int i = 0; i < SKEW; i++) {
        int s = fb + i;
        int sa = s < 0 ? 0 : s;
        float xv = xr[sa];
        xv = (s >= 0) ? xv : 0.f;
        (void)PSTEP(true, xv, i);
    }

    // ---------------- warm loop (no stores, masked loads, guarded GRU, ROLLED) ----------------
#pragma unroll 1
    for (int i = SKEW; i < WSTART; i += 4) {
        int s = fb + i;
        int sa = s < 0 ? 0 : s;                   // 4-aligned groups: all-in or all-out
        float4 v = *reinterpret_cast<const float4*>(xr + sa);
        float m = (s >= 0) ? 1.f : 0.f;
        float xv4[4] = { v.x * m, v.y * m, v.z * m, v.w * m };
#pragma unroll
        for (int j = 0; j < 4; j++)
            (void)PSTEP(true, xv4[j], i + j);
    }

    // ---------------- output loop (unconditional stores, ROLLED) ----------------
#pragma unroll 1
    for (int i = WSTART; i < ITERS; i += 4) {
        int s = fb + i;
        int sa = s > (L_TOTAL - 4) ? (L_TOTAL - 4) : s;  // tail over-read is dead data
        float4 v = *reinterpret_cast<const float4*>(xr + sa);
        float xv4[4] = { v.x, v.y, v.z, v.w };
        float ov4[4];
#pragma unroll
        for (int j = 0; j < 4; j++)
            ov4[j] = PSTEP(false, xv4[j], i + j);
        float4 o; o.x = ov4[0]; o.y = ov4[1]; o.z = ov4[2]; o.w = ov4[3];
        *reinterpret_cast<float4*>(orow + (s - SKEW)) = o;
    }
#undef PSTEP
}

extern "C" void kernel_launch(void* const* d_in, const int* in_sizes, int n_in,
                              void* d_out, int out_size)
{
    const float* X     = (const float*)d_in[0];
    const float* knobs = (const float*)d_in[1];
    const float* ecr   = (const float*)d_in[2];
    const float* prep  = (const float*)d_in[3];
    const float* postp = (const float*)d_in[4];
    const float* gwi   = (const float*)d_in[5];
    const float* gwh   = (const float*)d_in[6];
    const float* gbi   = (const float*)d_in[7];
    const float* gbh   = (const float*)d_in[8];
    const float* gow   = (const float*)d_in[9];
    const float* gob   = (const float*)d_in[10];
    const float* sw1   = (const float*)d_in[11];
    const float* sb1   = (const float*)d_in[12];
    const float* sw2   = (const float*)d_in[13];
    const float* sb2   = (const float*)d_in[14];
    const float* fw1   = (const float*)d_in[15];
    const float* fb1   = (const float*)d_in[16];
    const float* fw2   = (const float*)d_in[17];
    const float* fb2   = (const float*)d_in[18];
    const float* famt  = (const float*)d_in[19];
    float* OUT = (float*)d_out;

    dim3 grid(NTHREADS / BLOCK);   // 128 blocks x 512 threads: 4 warps per SMSP
    amp_kernel<<<grid, BLOCK>>>(X, knobs, ecr, prep, postp, gwi, gwh, gbi, gbh,
                                gow, gob, sw1, sb1, sw2, sb2, fw1, fb1, fw2, fb2,
                                famt, OUT);
}